// round 3
// baseline (speedup 1.0000x reference)
#include <cuda_runtime.h>
#include <mma.h>

using namespace nvcuda;

// ---------------------------------------------------------------------------
// Graph_drug: 2-stack GraphSAGE (sum aggr) + global mean pool + concat
//   mol:    N=200000, E=1e6,  dims 78 -> 156 -> 312 -> 128
//   clique: N=120000, E=5e5,  dims 92 -> 184 -> 368 -> 128
//   G=4096 graphs, out [G, 256] fp32
// GEMMs run on tensor cores via 3xTF32 (hi/lo split) for fp32-class accuracy.
// ---------------------------------------------------------------------------

#define GRAPHS 4096
#define SCRATCH_ELEMS 62500000
__device__ float g_bufA[SCRATCH_ELEMS];
__device__ float g_bufB[SCRATCH_ELEMS];
__device__ float g_agg [SCRATCH_ELEMS];
__device__ int   g_cnt [2 * GRAPHS];

// ---------------------------------------------------------------------------
__global__ void zero_f(float* __restrict__ p, size_t n) {
    size_t i = (size_t)blockIdx.x * blockDim.x + threadIdx.x;
    size_t stride = (size_t)gridDim.x * blockDim.x;
    for (; i < n; i += stride) p[i] = 0.0f;
}

// ---------------------------------------------------------------------------
// Edge scatter: agg[dst] += x[src].  One warp per edge; float2 lanes.
__global__ void scatter_add(const float* __restrict__ x,
                            const int* __restrict__ ei,
                            int E, int D2,          // D2 = D/2
                            float* __restrict__ agg) {
    int w = (blockIdx.x * blockDim.x + threadIdx.x) >> 5;
    int lane = threadIdx.x & 31;
    if (w >= E) return;
    int src = ei[w];
    int dst = ei[E + w];
    const float2* xs = (const float2*)(x + (size_t)src * (D2 * 2));
    float* ad = agg + (size_t)dst * (D2 * 2);
    for (int d = lane; d < D2; d += 32) {
        float2 v = xs[d];
        atomicAdd(ad + 2 * d,     v.x);
        atomicAdd(ad + 2 * d + 1, v.y);
    }
}

// ---------------------------------------------------------------------------
// Tensor-core SAGE GEMM (3xTF32): out = [relu](A0@W0^T [+ A1@W1^T] [+ bias])
//   A : [N, Din] row-major.  W : [Dout, Din] row-major.
// Block tile 64x64, BK=16, 8 warps, wmma m16n16k8.
#define BM 64
#define BN 64
#define BK 16
#define BKP 24
#define CSP 72

__global__ void sage_gemm_tc(const float* __restrict__ A0,
                             const float* __restrict__ A1,
                             const float* __restrict__ W0,
                             const float* __restrict__ W1,
                             const float* __restrict__ bias,
                             float* __restrict__ out,
                             int N, int Din, int Dout,
                             int dual, int doRelu) {
    __shared__ float As_hi[BM][BKP];
    __shared__ float As_lo[BM][BKP];
    __shared__ float Ws_hi[BN][BKP];
    __shared__ float Ws_lo[BN][BKP];
    __shared__ float Cs[BM][CSP];

    int tid = threadIdx.x;                 // 256 threads
    int rowBase = blockIdx.y * BM;
    int colBase = blockIdx.x * BN;

    int wid = tid >> 5;                    // 0..7
    int wm = wid & 3;                      // warp row tile (16 rows)
    int wn = wid >> 2;                     // warp col group (32 cols, 2 tiles)

    wmma::fragment<wmma::accumulator, 16, 16, 8, float> acc[2];
    wmma::fill_fragment(acc[0], 0.0f);
    wmma::fill_fragment(acc[1], 0.0f);

    int ldr = tid >> 2;                    // 0..63 (tile row / out col)
    int ldc = (tid & 3) * 4;               // 0,4,8,12

    int nPhases = dual ? 2 : 1;
    for (int ph = 0; ph < nPhases; ++ph) {
        const float* A = ph ? A1 : A0;
        const float* W = ph ? W1 : W0;
        for (int k0 = 0; k0 < Din; k0 += BK) {
            // Load + split A tile (64 x 16)
            int arow = rowBase + ldr;
            #pragma unroll
            for (int l = 0; l < 4; ++l) {
                int k = ldc + l;
                int kk = k0 + k;
                float v = (arow < N && kk < Din) ? A[(size_t)arow * Din + kk] : 0.0f;
                float hi = wmma::__float_to_tf32(v);
                As_hi[ldr][k] = hi;
                As_lo[ldr][k] = wmma::__float_to_tf32(v - hi);
            }
            // Load + split W tile (64 x 16)
            int wrow = colBase + ldr;
            #pragma unroll
            for (int l = 0; l < 4; ++l) {
                int k = ldc + l;
                int kk = k0 + k;
                float v = (wrow < Dout && kk < Din) ? W[(size_t)wrow * Din + kk] : 0.0f;
                float hi = wmma::__float_to_tf32(v);
                Ws_hi[ldr][k] = hi;
                Ws_lo[ldr][k] = wmma::__float_to_tf32(v - hi);
            }
            __syncthreads();

            #pragma unroll
            for (int k8 = 0; k8 < BK; k8 += 8) {
                wmma::fragment<wmma::matrix_a, 16, 16, 8, wmma::precision::tf32, wmma::row_major> a_hi, a_lo;
                wmma::load_matrix_sync(a_hi, &As_hi[wm * 16][k8], BKP);
                wmma::load_matrix_sync(a_lo, &As_lo[wm * 16][k8], BKP);
                #pragma unroll
                for (int t = 0; t < 2; ++t) {
                    wmma::fragment<wmma::matrix_b, 16, 16, 8, wmma::precision::tf32, wmma::col_major> b_hi, b_lo;
                    wmma::load_matrix_sync(b_hi, &Ws_hi[wn * 32 + t * 16][k8], BKP);
                    wmma::load_matrix_sync(b_lo, &Ws_lo[wn * 32 + t * 16][k8], BKP);
                    wmma::mma_sync(acc[t], a_hi, b_hi, acc[t]);
                    wmma::mma_sync(acc[t], a_hi, b_lo, acc[t]);
                    wmma::mma_sync(acc[t], a_lo, b_hi, acc[t]);
                }
            }
            __syncthreads();
        }
    }

    // Stage to smem, then bounded epilogue (bias + relu)
    wmma::store_matrix_sync(&Cs[wm * 16][wn * 32],      acc[0], CSP, wmma::mem_row_major);
    wmma::store_matrix_sync(&Cs[wm * 16][wn * 32 + 16], acc[1], CSP, wmma::mem_row_major);
    __syncthreads();

    #pragma unroll
    for (int l = 0; l < 16; ++l) {
        int idx = tid + l * 256;
        int m = idx >> 6;
        int n = idx & 63;
        int row = rowBase + m;
        int col = colBase + n;
        if (row < N && col < Dout) {
            float v = Cs[m][n];
            if (bias) v += bias[col];
            if (doRelu && v < 0.0f) v = 0.0f;
            out[(size_t)row * Dout + col] = v;
        }
    }
}

// ---------------------------------------------------------------------------
// Layer-3 finish: per node v = relu(aggU + R + bias); pooled-sum + count.
__global__ void l3_finish(const float* __restrict__ aggU,
                          const float* __restrict__ R,
                          const float* __restrict__ bias,
                          const int* __restrict__ batch,
                          int N, float* __restrict__ out, int colOff,
                          int* __restrict__ cnt) {
    int w = (blockIdx.x * blockDim.x + threadIdx.x) >> 5;
    int lane = threadIdx.x & 31;
    if (w >= N) return;
    int g = batch[w];
    const float* au = aggU + (size_t)w * 128;
    const float* rr = R + (size_t)w * 128;
    float* o = out + (size_t)g * 256 + colOff;
    #pragma unroll
    for (int c = lane; c < 128; c += 32) {
        float v = au[c] + rr[c] + bias[c];
        if (v < 0.0f) v = 0.0f;
        atomicAdd(o + c, v);
    }
    if (lane == 0) atomicAdd(cnt + g, 1);
}

// Divide pooled sums by counts.
__global__ void pool_div(float* __restrict__ out, const int* __restrict__ cnt) {
    int i = blockIdx.x * blockDim.x + threadIdx.x;
    if (i >= GRAPHS * 256) return;
    int g = i >> 8;
    int c = i & 255;
    int n = (c < 128) ? cnt[g] : cnt[GRAPHS + g];
    out[i] /= (float)(n > 0 ? n : 1);
}

// ---------------------------------------------------------------------------
static void run_stack(const float* x0, const int* ei, int E,
                      const int* batch, int N,
                      const float* const* Wp,   // wl1,bl1,wr1,wl2,bl2,wr2,wl3,bl3,wr3
                      int d0, int d1, int d2,   // d3 = 128
                      float* bufA, float* bufB, float* agg,
                      float* out, int colOff, int* cnt) {
    int sc_blocks = (int)(((long long)E * 32 + 255) / 256);
    int gy = (N + BM - 1) / BM;

    // Layer 1: agg = scatter(x0); h1 = relu(dualGEMM) -> bufA
    cudaMemsetAsync(agg, 0, (size_t)N * d0 * sizeof(float));
    scatter_add<<<sc_blocks, 256>>>(x0, ei, E, d0 / 2, agg);
    sage_gemm_tc<<<dim3((d1 + BN - 1) / BN, gy), 256>>>(
        agg, x0, Wp[0], Wp[2], Wp[1], bufA, N, d0, d1, 1, 1);

    // Layer 2: agg = scatter(h1); h2 = relu(dualGEMM) -> bufB
    cudaMemsetAsync(agg, 0, (size_t)N * d1 * sizeof(float));
    scatter_add<<<sc_blocks, 256>>>(bufA, ei, E, d1 / 2, agg);
    sage_gemm_tc<<<dim3((d2 + BN - 1) / BN, gy), 256>>>(
        agg, bufA, Wp[3], Wp[5], Wp[4], bufB, N, d1, d2, 1, 1);

    // Layer 3 (transform-first): U = h2@Wl^T, R = h2@Wr^T, then scatter U.
    float* U = bufA;
    float* R = bufA + 26000000;
    sage_gemm_tc<<<dim3(2, gy), 256>>>(
        bufB, nullptr, Wp[6], nullptr, nullptr, U, N, d2, 128, 0, 0);
    sage_gemm_tc<<<dim3(2, gy), 256>>>(
        bufB, nullptr, Wp[8], nullptr, nullptr, R, N, d2, 128, 0, 0);
    cudaMemsetAsync(agg, 0, (size_t)N * 128 * sizeof(float));
    scatter_add<<<sc_blocks, 256>>>(U, ei, E, 64, agg);
    l3_finish<<<(int)(((long long)N * 32 + 255) / 256), 256>>>(
        agg, R, Wp[7], batch, N, out, colOff, cnt);
}

extern "C" void kernel_launch(void* const* d_in, const int* in_sizes, int n_in,
                              void* d_out, int out_size) {
    const float* x      = (const float*)d_in[0];
    const int*   ei     = (const int*)d_in[1];
    const int*   batch  = (const int*)d_in[2];
    const float* xc     = (const float*)d_in[3];
    const int*   eic    = (const int*)d_in[4];
    const int*   batchc = (const int*)d_in[5];
    const float* W[18];
    for (int i = 0; i < 18; ++i) W[i] = (const float*)d_in[6 + i];
    float* out = (float*)d_out;

    int Nm = in_sizes[2];          // 200000
    int Em = in_sizes[1] / 2;      // 1000000
    int Nc = in_sizes[5];          // 120000
    int Ec = in_sizes[4] / 2;      // 500000

    float *bufA, *bufB, *agg;
    int* cnt;
    cudaGetSymbolAddress((void**)&bufA, g_bufA);
    cudaGetSymbolAddress((void**)&bufB, g_bufB);
    cudaGetSymbolAddress((void**)&agg,  g_agg);
    cudaGetSymbolAddress((void**)&cnt,  g_cnt);

    cudaMemsetAsync(out, 0, (size_t)GRAPHS * 256 * sizeof(float));
    cudaMemsetAsync(cnt, 0, 2 * GRAPHS * sizeof(int));

    // Molecular stack -> out cols [0,128)
    run_stack(x, ei, Em, batch, Nm, W + 0, 78, 156, 312,
              bufA, bufB, agg, out, 0, cnt);

    // Clique stack -> out cols [128,256)
    run_stack(xc, eic, Ec, batchc, Nc, W + 9, 92, 184, 368,
              bufA, bufB, agg, out, 128, cnt + GRAPHS);

    // Mean
    pool_div<<<(GRAPHS * 256 + 255) / 256, 256>>>(out, cnt);
}

// round 4
// speedup vs baseline: 1.6529x; 1.6529x over previous
#include <cuda_runtime.h>

// ---------------------------------------------------------------------------
// Graph_drug: 2-stack GraphSAGE (sum aggr) + global mean pool + concat
//   mol:    N=200000, E=1e6,  dims 78 -> 156 -> 312 -> 128
//   clique: N=120000, E=5e5,  dims 92 -> 184 -> 368 -> 128
//   G=4096 graphs, out [G, 256] fp32
// fp32 SIMT GEMM with 128x64 tiles; layer 3 is transform-first (scatter at 128).
// ---------------------------------------------------------------------------

#define GRAPHS 4096
#define SCRATCH_ELEMS 62500000
__device__ float g_bufA[SCRATCH_ELEMS];
__device__ float g_bufB[SCRATCH_ELEMS];
__device__ float g_agg [SCRATCH_ELEMS];
__device__ int   g_cnt [2 * GRAPHS];

// ---------------------------------------------------------------------------
// Edge scatter: agg[dst] += x[src].  One warp per edge; float2 lanes.
__global__ void scatter_add(const float* __restrict__ x,
                            const int* __restrict__ ei,
                            int E, int D2,          // D2 = D/2
                            float* __restrict__ agg) {
    int w = (blockIdx.x * blockDim.x + threadIdx.x) >> 5;
    int lane = threadIdx.x & 31;
    if (w >= E) return;
    int src = ei[w];
    int dst = ei[E + w];
    const float2* xs = (const float2*)(x + (size_t)src * (D2 * 2));
    float* ad = agg + (size_t)dst * (D2 * 2);
    for (int d = lane; d < D2; d += 32) {
        float2 v = xs[d];
        atomicAdd(ad + 2 * d,     v.x);
        atomicAdd(ad + 2 * d + 1, v.y);
    }
}

// ---------------------------------------------------------------------------
// Fused SAGE GEMM: out = [relu](A0@W0^T [+ A1@W1^T] [+ bias])
//   A : [N, Din] row-major.  W : [Dout, Din] row-major.
// 128x64x16 tile, 256 threads, 8x4 register tile per thread.
#define BM 128
#define BN 64
#define BK 16

__global__ __launch_bounds__(256)
void sage_gemm(const float* __restrict__ A0,
               const float* __restrict__ A1,
               const float* __restrict__ W0,
               const float* __restrict__ W1,
               const float* __restrict__ bias,
               float* __restrict__ out,
               int N, int Din, int Dout,
               int dual, int doRelu) {
    __shared__ float As[BK][BM];
    __shared__ float Ws[BK][BN];

    int tid = threadIdx.x;                 // 0..255
    int tr = tid >> 4;                     // 0..15 -> rows tr*8..tr*8+7
    int tc = tid & 15;                     // 0..15 -> cols tc*4..tc*4+3
    int rowBase = blockIdx.y * BM;
    int colBase = blockIdx.x * BN;

    float acc[8][4];
    #pragma unroll
    for (int i = 0; i < 8; ++i)
        #pragma unroll
        for (int j = 0; j < 4; ++j) acc[i][j] = 0.0f;

    int nPhases = dual ? 2 : 1;
    for (int ph = 0; ph < nPhases; ++ph) {
        const float* A = ph ? A1 : A0;
        const float* W = ph ? W1 : W0;
        for (int k0 = 0; k0 < Din; k0 += BK) {
            // A tile: 128 rows x 16 k = 2048 elems, 8 per thread.
            #pragma unroll
            for (int l = 0; l < 8; ++l) {
                int idx = tid * 8 + l;
                int m = idx >> 4;
                int k = idx & 15;
                int row = rowBase + m;
                int kk = k0 + k;
                As[k][m] = (row < N && kk < Din) ? A[(size_t)row * Din + kk] : 0.0f;
            }
            // W tile: 64 cols x 16 k = 1024 elems, 4 per thread.
            #pragma unroll
            for (int l = 0; l < 4; ++l) {
                int idx = tid * 4 + l;
                int n = idx >> 4;
                int k = idx & 15;
                int col = colBase + n;
                int kk = k0 + k;
                Ws[k][n] = (col < Dout && kk < Din) ? W[(size_t)col * Din + kk] : 0.0f;
            }
            __syncthreads();

            #pragma unroll
            for (int k = 0; k < BK; ++k) {
                float4 a0 = *(const float4*)&As[k][tr * 8];
                float4 a1 = *(const float4*)&As[k][tr * 8 + 4];
                float4 b  = *(const float4*)&Ws[k][tc * 4];
                float a[8] = {a0.x, a0.y, a0.z, a0.w, a1.x, a1.y, a1.z, a1.w};
                float bb[4] = {b.x, b.y, b.z, b.w};
                #pragma unroll
                for (int i = 0; i < 8; ++i)
                    #pragma unroll
                    for (int j = 0; j < 4; ++j)
                        acc[i][j] += a[i] * bb[j];
            }
            __syncthreads();
        }
    }

    // Epilogue: direct float4 stores (all Dout are multiples of 4).
    int col = colBase + tc * 4;
    if (col < Dout) {
        float4 bv = make_float4(0.f, 0.f, 0.f, 0.f);
        if (bias) bv = *(const float4*)&bias[col];
        #pragma unroll
        for (int i = 0; i < 8; ++i) {
            int row = rowBase + tr * 8 + i;
            if (row >= N) continue;
            float4 v;
            v.x = acc[i][0] + bv.x;
            v.y = acc[i][1] + bv.y;
            v.z = acc[i][2] + bv.z;
            v.w = acc[i][3] + bv.w;
            if (doRelu) {
                v.x = v.x > 0.f ? v.x : 0.f;
                v.y = v.y > 0.f ? v.y : 0.f;
                v.z = v.z > 0.f ? v.z : 0.f;
                v.w = v.w > 0.f ? v.w : 0.f;
            }
            *(float4*)&out[(size_t)row * Dout + col] = v;
        }
    }
}

// ---------------------------------------------------------------------------
// Layer-3 finish: per node v = relu(aggU + R + bias); pooled-sum + count.
__global__ void l3_finish(const float* __restrict__ aggU,
                          const float* __restrict__ R,
                          const float* __restrict__ bias,
                          const int* __restrict__ batch,
                          int N, float* __restrict__ out, int colOff,
                          int* __restrict__ cnt) {
    int w = (blockIdx.x * blockDim.x + threadIdx.x) >> 5;
    int lane = threadIdx.x & 31;
    if (w >= N) return;
    int g = batch[w];
    const float* au = aggU + (size_t)w * 128;
    const float* rr = R + (size_t)w * 128;
    float* o = out + (size_t)g * 256 + colOff;
    #pragma unroll
    for (int c = lane; c < 128; c += 32) {
        float v = au[c] + rr[c] + bias[c];
        if (v < 0.0f) v = 0.0f;
        atomicAdd(o + c, v);
    }
    if (lane == 0) atomicAdd(cnt + g, 1);
}

// Divide pooled sums by counts.
__global__ void pool_div(float* __restrict__ out, const int* __restrict__ cnt) {
    int i = blockIdx.x * blockDim.x + threadIdx.x;
    if (i >= GRAPHS * 256) return;
    int g = i >> 8;
    int c = i & 255;
    int n = (c < 128) ? cnt[g] : cnt[GRAPHS + g];
    out[i] /= (float)(n > 0 ? n : 1);
}

// ---------------------------------------------------------------------------
static void run_stack(const float* x0, const int* ei, int E,
                      const int* batch, int N,
                      const float* const* Wp,   // wl1,bl1,wr1,wl2,bl2,wr2,wl3,bl3,wr3
                      int d0, int d1, int d2,   // d3 = 128
                      float* bufA, float* bufB, float* agg,
                      float* out, int colOff, int* cnt) {
    int sc_blocks = (int)(((long long)E * 32 + 255) / 256);
    int gy = (N + BM - 1) / BM;

    // Layer 1: agg = scatter(x0); h1 = relu(dualGEMM) -> bufA
    cudaMemsetAsync(agg, 0, (size_t)N * d0 * sizeof(float));
    scatter_add<<<sc_blocks, 256>>>(x0, ei, E, d0 / 2, agg);
    sage_gemm<<<dim3((d1 + BN - 1) / BN, gy), 256>>>(
        agg, x0, Wp[0], Wp[2], Wp[1], bufA, N, d0, d1, 1, 1);

    // Layer 2: agg = scatter(h1); h2 = relu(dualGEMM) -> bufB
    cudaMemsetAsync(agg, 0, (size_t)N * d1 * sizeof(float));
    scatter_add<<<sc_blocks, 256>>>(bufA, ei, E, d1 / 2, agg);
    sage_gemm<<<dim3((d2 + BN - 1) / BN, gy), 256>>>(
        agg, bufA, Wp[3], Wp[5], Wp[4], bufB, N, d1, d2, 1, 1);

    // Layer 3 (transform-first): U = h2@Wl^T, R = h2@Wr^T, scatter U at D=128.
    float* U = bufA;
    float* R = bufA + 26000000;
    sage_gemm<<<dim3(2, gy), 256>>>(
        bufB, nullptr, Wp[6], nullptr, nullptr, U, N, d2, 128, 0, 0);
    sage_gemm<<<dim3(2, gy), 256>>>(
        bufB, nullptr, Wp[8], nullptr, nullptr, R, N, d2, 128, 0, 0);
    cudaMemsetAsync(agg, 0, (size_t)N * 128 * sizeof(float));
    scatter_add<<<sc_blocks, 256>>>(U, ei, E, 64, agg);
    l3_finish<<<(int)(((long long)N * 32 + 255) / 256), 256>>>(
        agg, R, Wp[7], batch, N, out, colOff, cnt);
}

extern "C" void kernel_launch(void* const* d_in, const int* in_sizes, int n_in,
                              void* d_out, int out_size) {
    const float* x      = (const float*)d_in[0];
    const int*   ei     = (const int*)d_in[1];
    const int*   batch  = (const int*)d_in[2];
    const float* xc     = (const float*)d_in[3];
    const int*   eic    = (const int*)d_in[4];
    const int*   batchc = (const int*)d_in[5];
    const float* W[18];
    for (int i = 0; i < 18; ++i) W[i] = (const float*)d_in[6 + i];
    float* out = (float*)d_out;

    int Nm = in_sizes[2];          // 200000
    int Em = in_sizes[1] / 2;      // 1000000
    int Nc = in_sizes[5];          // 120000
    int Ec = in_sizes[4] / 2;      // 500000

    float *bufA, *bufB, *agg;
    int* cnt;
    cudaGetSymbolAddress((void**)&bufA, g_bufA);
    cudaGetSymbolAddress((void**)&bufB, g_bufB);
    cudaGetSymbolAddress((void**)&agg,  g_agg);
    cudaGetSymbolAddress((void**)&cnt,  g_cnt);

    cudaMemsetAsync(out, 0, (size_t)GRAPHS * 256 * sizeof(float));
    cudaMemsetAsync(cnt, 0, 2 * GRAPHS * sizeof(int));

    // Molecular stack -> out cols [0,128)
    run_stack(x, ei, Em, batch, Nm, W + 0, 78, 156, 312,
              bufA, bufB, agg, out, 0, cnt);

    // Clique stack -> out cols [128,256)
    run_stack(xc, eic, Ec, batchc, Nc, W + 9, 92, 184, 368,
              bufA, bufB, agg, out, 128, cnt + GRAPHS);

    // Mean
    pool_div<<<(GRAPHS * 256 + 255) / 256, 256>>>(out, cnt);
}